// round 15
// baseline (speedup 1.0000x reference)
#include <cuda_runtime.h>
#include <cuda_bf16.h>

#define THREADS  256
#define ITEMS    8
#define FULLMASK 0xffffffffu

__global__ void init_out_kernel(float* __restrict__ y,
                                const float* __restrict__ bias, int n) {
    int i  = blockIdx.x * blockDim.x + threadIdx.x;
    int i4 = i * 4;
    if (i4 + 4 <= n) {
        float4 b = *reinterpret_cast<const float4*>(bias + i4);
        *reinterpret_cast<float4*>(y + i4) = b;
    } else if (i4 < n) {
        for (int k = i4; k < n; k++) y[k] = bias[k];
    }
}

__global__ __launch_bounds__(THREADS)
void spmv_coo_kernel(const float* __restrict__ vals,
                     const float* __restrict__ x,
                     const int*   __restrict__ rows,
                     const int*   __restrict__ cols,
                     float*       __restrict__ y,
                     unsigned nnz) {
    const unsigned tid  = blockIdx.x * THREADS + threadIdx.x;
    const unsigned base = tid * ITEMS;
    const int lane = threadIdx.x & 31;
    // Warp-uniform predicate: is this warp's whole 256-nnz span in range?
    const unsigned warpBase = (tid & ~31u) * ITEMS;
    const bool warpFull = (warpBase + 32u * ITEMS) <= nnz;

    if (warpFull) {
        // ---- Streaming loads: evict-first (__ldcs) so x keeps L1 residency.
        //      These (and the gathers below) overlap with the still-running
        //      init kernel thanks to PDL. ----
        const int4*   rp = reinterpret_cast<const int4*>(rows + base);
        const int4*   cp = reinterpret_cast<const int4*>(cols + base);
        const float4* vp = reinterpret_cast<const float4*>(vals + base);

        int4   c0 = __ldcs(&cp[0]);
        int4   c1 = __ldcs(&cp[1]);
        int4   r0 = __ldcs(&rp[0]);
        int4   r1 = __ldcs(&rp[1]);
        float4 v0 = __ldcs(&vp[0]);
        float4 v1 = __ldcs(&vp[1]);

        // ---- Gather x: 8 independent random 4B loads ----
        float xv[ITEMS];
        xv[0] = __ldg(&x[c0.x]);
        xv[1] = __ldg(&x[c0.y]);
        xv[2] = __ldg(&x[c0.z]);
        xv[3] = __ldg(&x[c0.w]);
        xv[4] = __ldg(&x[c1.x]);
        xv[5] = __ldg(&x[c1.y]);
        xv[6] = __ldg(&x[c1.z]);
        xv[7] = __ldg(&x[c1.w]);

        int   r[ITEMS] = {r0.x, r0.y, r0.z, r0.w, r1.x, r1.y, r1.z, r1.w};
        float v[ITEMS] = {v0.x, v0.y, v0.z, v0.w, v1.x, v1.y, v1.z, v1.w};

        // ---- Wait for init kernel (y = bias) before the first atomic ----
        cudaGridDependencySynchronize();

        // ---- Per-thread segment scan; direct atomic on each boundary
        //      (boundaries occur in only ~12% of chunks) ----
        float acc = 0.0f;
        int   cur = r[0];
        #pragma unroll
        for (int i = 0; i < ITEMS; i++) {
            if (r[i] != cur) {
                atomicAdd(&y[cur], acc);
                acc = 0.0f;
                cur = r[i];
            }
            acc = fmaf(v[i], xv[i], acc);
        }

        // ---- Warp segmented inclusive scan over tail accumulators.
        //      Rows sorted => equal tail rows are lane-contiguous. ----
        int lrprev = __shfl_up_sync(FULLMASK, cur, 1);
        unsigned headf = (lane == 0) || (cur != lrprev);

        float    vsum = acc;
        unsigned stop = headf;
        #pragma unroll
        for (int d = 1; d < 32; d <<= 1) {
            float    pv = __shfl_up_sync(FULLMASK, vsum, d);
            unsigned ps = __shfl_up_sync(FULLMASK, stop, d);
            if (lane >= d && !stop) { vsum += pv; stop = ps; }
        }
        unsigned hnext = __shfl_down_sync(FULLMASK, headf, 1);
        if (lane == 31 || hnext) atomicAdd(&y[cur], vsum);
    } else {
        // ---- Tail warp: scalar, bounds-checked, no collectives ----
        if (base >= nnz) return;
        cudaGridDependencySynchronize();
        unsigned end = base + ITEMS;
        if (end > nnz) end = nnz;
        float acc = 0.0f;
        int   cur = rows[base];
        for (unsigned i = base; i < end; i++) {
            int   ri = rows[i];
            int   ci = cols[i];
            float vi = vals[i];
            if (ri != cur) {
                atomicAdd(&y[cur], acc);
                acc = 0.0f;
                cur = ri;
            }
            acc = fmaf(vi, __ldg(&x[ci]), acc);
        }
        atomicAdd(&y[cur], acc);
    }
}

extern "C" void kernel_launch(void* const* d_in, const int* in_sizes, int n_in,
                              void* d_out, int out_size) {
    // metadata order: vals[NNZ] f32, x[N_COLS] f32, bias[N_ROWS] f32,
    //                 rows[NNZ] i32, cols[NNZ] i32, n_rows (ignored)
    const float* vals = (const float*)d_in[0];
    const float* x    = (const float*)d_in[1];
    const float* bias = (const float*)d_in[2];
    const int*   rows = (const int*)d_in[3];
    const int*   cols = (const int*)d_in[4];
    float* y = (float*)d_out;

    unsigned nnz = (unsigned)in_sizes[0];
    int n_rows   = in_sizes[2];

    // 1) y = bias  (vectorized; d_out is poisoned before timing)
    {
        int quads = (n_rows + 3) / 4;
        int grid  = (quads + THREADS - 1) / THREADS;
        init_out_kernel<<<grid, THREADS>>>(y, bias, n_rows);
    }

    // 2) y += segment_sum(vals * x[cols]) — PDL launch: starts while init is
    //    still running; device-side cudaGridDependencySynchronize() orders the
    //    atomics after init's completion.
    {
        unsigned chunks = (nnz + ITEMS - 1) / ITEMS;
        unsigned grid   = (chunks + THREADS - 1) / THREADS;

        cudaLaunchConfig_t cfg = {};
        cfg.gridDim  = dim3(grid, 1, 1);
        cfg.blockDim = dim3(THREADS, 1, 1);
        cfg.dynamicSmemBytes = 0;
        cfg.stream = 0;

        cudaLaunchAttribute attrs[1];
        attrs[0].id = cudaLaunchAttributeProgrammaticStreamSerialization;
        attrs[0].val.programmaticStreamSerializationAllowed = 1;
        cfg.attrs = attrs;
        cfg.numAttrs = 1;

        cudaLaunchKernelEx(&cfg, spmv_coo_kernel, vals, x, rows, cols, y, nnz);
    }
}

// round 16
// speedup vs baseline: 1.0705x; 1.0705x over previous
#include <cuda_runtime.h>
#include <cuda_bf16.h>

#define THREADS  256
#define ITEMS    8
#define FULLMASK 0xffffffffu

__global__ __launch_bounds__(THREADS)
void spmv_coo_kernel(const float* __restrict__ vals,
                     const float* __restrict__ x,
                     const int*   __restrict__ rows,
                     const int*   __restrict__ cols,
                     float*       __restrict__ y,
                     unsigned nnz) {
    const unsigned tid  = blockIdx.x * THREADS + threadIdx.x;
    const unsigned base = tid * ITEMS;
    const int lane = threadIdx.x & 31;
    // Warp-uniform predicate: is this warp's whole 256-nnz span in range?
    const unsigned warpBase = (tid & ~31u) * ITEMS;
    const bool warpFull = (warpBase + 32u * ITEMS) <= nnz;

    if (warpFull) {
        // ---- Streaming loads: evict-first (__ldcs) so x keeps L1 residency ----
        const int4*   rp = reinterpret_cast<const int4*>(rows + base);
        const int4*   cp = reinterpret_cast<const int4*>(cols + base);
        const float4* vp = reinterpret_cast<const float4*>(vals + base);

        int4   c0 = __ldcs(&cp[0]);
        int4   c1 = __ldcs(&cp[1]);
        int4   r0 = __ldcs(&rp[0]);
        int4   r1 = __ldcs(&rp[1]);
        float4 v0 = __ldcs(&vp[0]);
        float4 v1 = __ldcs(&vp[1]);

        // ---- Gather x: 8 independent random 4B loads ----
        float xv[ITEMS];
        xv[0] = __ldg(&x[c0.x]);
        xv[1] = __ldg(&x[c0.y]);
        xv[2] = __ldg(&x[c0.z]);
        xv[3] = __ldg(&x[c0.w]);
        xv[4] = __ldg(&x[c1.x]);
        xv[5] = __ldg(&x[c1.y]);
        xv[6] = __ldg(&x[c1.z]);
        xv[7] = __ldg(&x[c1.w]);

        int   r[ITEMS] = {r0.x, r0.y, r0.z, r0.w, r1.x, r1.y, r1.z, r1.w};
        float v[ITEMS] = {v0.x, v0.y, v0.z, v0.w, v1.x, v1.y, v1.z, v1.w};

        // ---- Per-thread segment scan; direct atomic on each boundary
        //      (boundaries occur in only ~12% of chunks) ----
        float acc = 0.0f;
        int   cur = r[0];
        #pragma unroll
        for (int i = 0; i < ITEMS; i++) {
            if (r[i] != cur) {
                atomicAdd(&y[cur], acc);
                acc = 0.0f;
                cur = r[i];
            }
            acc = fmaf(v[i], xv[i], acc);
        }

        // ---- Warp segmented inclusive scan over tail accumulators.
        //      Rows sorted => equal tail rows are lane-contiguous. ----
        int lrprev = __shfl_up_sync(FULLMASK, cur, 1);
        unsigned headf = (lane == 0) || (cur != lrprev);

        float    vsum = acc;
        unsigned stop = headf;
        #pragma unroll
        for (int d = 1; d < 32; d <<= 1) {
            float    pv = __shfl_up_sync(FULLMASK, vsum, d);
            unsigned ps = __shfl_up_sync(FULLMASK, stop, d);
            if (lane >= d && !stop) { vsum += pv; stop = ps; }
        }
        unsigned hnext = __shfl_down_sync(FULLMASK, headf, 1);
        if (lane == 31 || hnext) atomicAdd(&y[cur], vsum);
    } else {
        // ---- Tail warp: scalar, bounds-checked, no collectives ----
        if (base >= nnz) return;
        unsigned end = base + ITEMS;
        if (end > nnz) end = nnz;
        float acc = 0.0f;
        int   cur = rows[base];
        for (unsigned i = base; i < end; i++) {
            int   ri = rows[i];
            int   ci = cols[i];
            float vi = vals[i];
            if (ri != cur) {
                atomicAdd(&y[cur], acc);
                acc = 0.0f;
                cur = ri;
            }
            acc = fmaf(vi, __ldg(&x[ci]), acc);
        }
        atomicAdd(&y[cur], acc);
    }
}

extern "C" void kernel_launch(void* const* d_in, const int* in_sizes, int n_in,
                              void* d_out, int out_size) {
    // metadata order: vals[NNZ] f32, x[N_COLS] f32, bias[N_ROWS] f32,
    //                 rows[NNZ] i32, cols[NNZ] i32, n_rows (ignored)
    const float* vals = (const float*)d_in[0];
    const float* x    = (const float*)d_in[1];
    const float* bias = (const float*)d_in[2];
    const int*   rows = (const int*)d_in[3];
    const int*   cols = (const int*)d_in[4];
    float* y = (float*)d_out;

    unsigned nnz = (unsigned)in_sizes[0];
    int n_rows   = in_sizes[2];

    // 1) y = bias — async D2D copy node (cheaper than a kernel launch;
    //    d_out is poisoned before timing so this also initializes it)
    cudaMemcpyAsync(y, bias, (size_t)n_rows * sizeof(float),
                    cudaMemcpyDeviceToDevice, 0);

    // 2) y += segment_sum(vals * x[cols]) — flat launch, one 8-nnz chunk/thread
    {
        unsigned chunks = (nnz + ITEMS - 1) / ITEMS;
        unsigned grid   = (chunks + THREADS - 1) / THREADS;
        spmv_coo_kernel<<<grid, THREADS>>>(vals, x, rows, cols, y, nnz);
    }
}